// round 3
// baseline (speedup 1.0000x reference)
#include <cuda_runtime.h>
#include <math.h>

// ---------------------------------------------------------------------------
// TransformerXL relative positional encoding scores.
//   Q = x@Wq^T ; K = x@Wk^T ; R = table@Wr^T
//   content = (Q+u) @ K^T            (per batch)
//   A       = (Q+v) @ R^T            (B*L x 2M+1)
//   out[b,l,j] = (content[b,l,j] + A[b,l, clip(l-j,-M,M)+M]) / sqrt(D)
// Shapes: B=4, L=2048, D=1024, M=512.
// ---------------------------------------------------------------------------

#define BM 128
#define BN 128
#define BK 8

// Scratch (device globals; allocation-free per harness rules)
__device__ float g_Qu[(size_t)8192 * 1024];
__device__ float g_Qv[(size_t)8192 * 1024];
__device__ float g_Kb[(size_t)8192 * 1024];
__device__ float g_R [(size_t)1056 * 1024];
__device__ float g_A [(size_t)8192 * 1028];   // ld = 1028 (16B aligned rows)

// MODE 0: C = A@B^T
// MODE 1: C = A@B^T + u[n], C2 = A@B^T + v[n]
// MODE 2: batched content with relative-position gather epilogue
template<int MODE, bool BOUNDS>
__global__ void __launch_bounds__(256)
sgemm_k(const float* __restrict__ Ag, const float* __restrict__ Bg,
        float* __restrict__ C, float* __restrict__ C2,
        int M, int N, int K, int ldc,
        const float* __restrict__ uvec, const float* __restrict__ vvec,
        const float* __restrict__ Amat, int ldA, int L, int maxrel, float scale)
{
    const int tid = threadIdx.x;
    const int tx = tid & 15;          // 0..15 -> col groups
    const int ty = tid >> 4;          // 0..15 -> row groups

    if (MODE == 2) {
        size_t off = (size_t)blockIdx.z * (size_t)L * (size_t)K;
        Ag += off;
        Bg += off;
    }

    __shared__ float As[2][BK][BM];
    __shared__ float Bs[2][BK][BN];

    const int row0 = blockIdx.y * BM;
    const int col0 = blockIdx.x * BN;

    // global load mapping: 256 threads, one float4 of A and one of B each
    const int lr = tid >> 1;          // 0..127 (row within tile)
    const int lk = (tid & 1) * 4;     // 0 or 4 (k within BK)

    const int numT = K / BK;          // K is always a multiple of BK here

    float4 aReg, bReg;

    // prologue: tile 0 -> smem[0]
    {
        int ar = row0 + lr;
        int br = col0 + lr;
        const float* ap = Ag + (size_t)ar * K + lk;
        const float* bp = Bg + (size_t)br * K + lk;
        if (BOUNDS) {
            aReg = (ar < M) ? *reinterpret_cast<const float4*>(ap) : make_float4(0.f,0.f,0.f,0.f);
            bReg = (br < N) ? *reinterpret_cast<const float4*>(bp) : make_float4(0.f,0.f,0.f,0.f);
        } else {
            aReg = *reinterpret_cast<const float4*>(ap);
            bReg = *reinterpret_cast<const float4*>(bp);
        }
        As[0][lk+0][lr] = aReg.x; As[0][lk+1][lr] = aReg.y;
        As[0][lk+2][lr] = aReg.z; As[0][lk+3][lr] = aReg.w;
        Bs[0][lk+0][lr] = bReg.x; Bs[0][lk+1][lr] = bReg.y;
        Bs[0][lk+2][lr] = bReg.z; Bs[0][lk+3][lr] = bReg.w;
    }
    __syncthreads();

    float acc[8][8];
    #pragma unroll
    for (int i = 0; i < 8; ++i)
        #pragma unroll
        for (int j = 0; j < 8; ++j) acc[i][j] = 0.f;

    int buf = 0;
    for (int t = 0; t < numT; ++t) {
        // prefetch next tile to registers
        if (t + 1 < numT) {
            int kk = (t + 1) * BK + lk;
            int ar = row0 + lr;
            int br = col0 + lr;
            const float* ap = Ag + (size_t)ar * K + kk;
            const float* bp = Bg + (size_t)br * K + kk;
            if (BOUNDS) {
                aReg = (ar < M) ? *reinterpret_cast<const float4*>(ap) : make_float4(0.f,0.f,0.f,0.f);
                bReg = (br < N) ? *reinterpret_cast<const float4*>(bp) : make_float4(0.f,0.f,0.f,0.f);
            } else {
                aReg = *reinterpret_cast<const float4*>(ap);
                bReg = *reinterpret_cast<const float4*>(bp);
            }
        }

        #pragma unroll
        for (int k = 0; k < BK; ++k) {
            float4 a0 = *reinterpret_cast<const float4*>(&As[buf][k][ty * 4]);
            float4 a1 = *reinterpret_cast<const float4*>(&As[buf][k][64 + ty * 4]);
            float4 b0 = *reinterpret_cast<const float4*>(&Bs[buf][k][tx * 4]);
            float4 b1 = *reinterpret_cast<const float4*>(&Bs[buf][k][64 + tx * 4]);
            float af[8] = {a0.x,a0.y,a0.z,a0.w,a1.x,a1.y,a1.z,a1.w};
            float bf[8] = {b0.x,b0.y,b0.z,b0.w,b1.x,b1.y,b1.z,b1.w};
            #pragma unroll
            for (int i = 0; i < 8; ++i)
                #pragma unroll
                for (int j = 0; j < 8; ++j)
                    acc[i][j] = fmaf(af[i], bf[j], acc[i][j]);
        }

        if (t + 1 < numT) {
            int nb = buf ^ 1;
            As[nb][lk+0][lr] = aReg.x; As[nb][lk+1][lr] = aReg.y;
            As[nb][lk+2][lr] = aReg.z; As[nb][lk+3][lr] = aReg.w;
            Bs[nb][lk+0][lr] = bReg.x; Bs[nb][lk+1][lr] = bReg.y;
            Bs[nb][lk+2][lr] = bReg.z; Bs[nb][lk+3][lr] = bReg.w;
            __syncthreads();
            buf = nb;
        }
    }

    // ---------------- epilogue ----------------
    const int rb[2] = { row0 + ty * 4, row0 + 64 + ty * 4 };
    const int cb[2] = { col0 + tx * 4, col0 + 64 + tx * 4 };

    #pragma unroll
    for (int ih = 0; ih < 2; ++ih) {
        #pragma unroll
        for (int ii = 0; ii < 4; ++ii) {
            const int r = rb[ih] + ii;
            const int i = ih * 4 + ii;
            if (BOUNDS && r >= M) continue;

            if (MODE == 2) {
                const size_t grow = (size_t)(blockIdx.z * L + r);
                const float* arow = Amat + grow * (size_t)ldA + maxrel;
                float* crow = C + grow * (size_t)ldc;
                #pragma unroll
                for (int jh = 0; jh < 2; ++jh) {
                    const int c0 = cb[jh];
                    const int d0 = r - c0;
                    float4 o;
                    float* po = &o.x;
                    #pragma unroll
                    for (int jj = 0; jj < 4; ++jj) {
                        int d = d0 - jj;
                        d = d < -maxrel ? -maxrel : (d > maxrel ? maxrel : d);
                        po[jj] = (acc[i][jh * 4 + jj] + arow[d]) * scale;
                    }
                    *reinterpret_cast<float4*>(crow + c0) = o;
                }
            } else if (MODE == 1) {
                float* crow  = C  + (size_t)r * ldc;
                float* c2row = C2 + (size_t)r * ldc;
                #pragma unroll
                for (int jh = 0; jh < 2; ++jh) {
                    const int c0 = cb[jh];
                    float4 o1, o2;
                    float* p1 = &o1.x;
                    float* p2 = &o2.x;
                    #pragma unroll
                    for (int jj = 0; jj < 4; ++jj) {
                        float a = acc[i][jh * 4 + jj];
                        p1[jj] = a + uvec[c0 + jj];
                        p2[jj] = a + vvec[c0 + jj];
                    }
                    *reinterpret_cast<float4*>(crow  + c0) = o1;
                    *reinterpret_cast<float4*>(c2row + c0) = o2;
                }
            } else { // MODE 0
                float* crow = C + (size_t)r * ldc;
                if (!BOUNDS) {
                    #pragma unroll
                    for (int jh = 0; jh < 2; ++jh) {
                        const int c0 = cb[jh];
                        float4 o;
                        float* po = &o.x;
                        #pragma unroll
                        for (int jj = 0; jj < 4; ++jj)
                            po[jj] = acc[i][jh * 4 + jj];
                        *reinterpret_cast<float4*>(crow + c0) = o;
                    }
                } else {
                    #pragma unroll
                    for (int jh = 0; jh < 2; ++jh) {
                        #pragma unroll
                        for (int jj = 0; jj < 4; ++jj) {
                            const int c = cb[jh] + jj;
                            if (c < N) crow[c] = acc[i][jh * 4 + jj];
                        }
                    }
                }
            }
        }
    }
}

extern "C" void kernel_launch(void* const* d_in, const int* in_sizes, int n_in,
                              void* d_out, int out_size)
{
    const float* x     = (const float*)d_in[0];
    const float* Wq    = (const float*)d_in[1];
    const float* Wk    = (const float*)d_in[2];
    const float* Wr    = (const float*)d_in[3];
    const float* u     = (const float*)d_in[4];
    const float* v     = (const float*)d_in[5];
    const float* table = (const float*)d_in[6];
    float* out = (float*)d_out;

    // Derive shapes (D exactly from u's length; no float rounding)
    const int D      = in_sizes[4];                              // 1024
    const int ML     = in_sizes[0] / D;                          // B*L = 8192
    const int L      = out_size / ML;                            // 2048
    const int Bb     = ML / L;                                   // 4
    const int twoM1  = in_sizes[6] / D;                          // 1025
    const int maxrel = (twoM1 - 1) / 2;                          // 512
    const int ldA    = 1028;                                     // padded A ld
    const float scale = 1.0f / sqrtf((float)D);

    // One-time symbol lookups (host-side cache; deterministic, capture-safe)
    static float *pQu = nullptr, *pQv = nullptr, *pK = nullptr,
                 *pR = nullptr, *pA = nullptr;
    if (!pQu) {
        cudaGetSymbolAddress((void**)&pQu, g_Qu);
        cudaGetSymbolAddress((void**)&pQv, g_Qv);
        cudaGetSymbolAddress((void**)&pK,  g_Kb);
        cudaGetSymbolAddress((void**)&pR,  g_R);
        cudaGetSymbolAddress((void**)&pA,  g_A);
    }

    dim3 blk(256);

    // 1) Q = x@Wq^T ; Qu = Q+u, Qv = Q+v     (8192 x 1024)
    {
        dim3 grid(D / BN, ML / BM);
        sgemm_k<1, false><<<grid, blk>>>(x, Wq, pQu, pQv, ML, D, D, D,
                                         u, v, nullptr, 0, 0, 0, 0.f);
    }
    // 2) K = x@Wk^T                           (8192 x 1024)
    {
        dim3 grid(D / BN, ML / BM);
        sgemm_k<0, false><<<grid, blk>>>(x, Wk, pK, nullptr, ML, D, D, D,
                                         nullptr, nullptr, nullptr, 0, 0, 0, 0.f);
    }
    // 3) R = table@Wr^T                       (1025 x 1024)
    {
        dim3 grid(D / BN, (twoM1 + BM - 1) / BM);
        sgemm_k<0, true><<<grid, blk>>>(table, Wr, pR, nullptr, twoM1, D, D, D,
                                        nullptr, nullptr, nullptr, 0, 0, 0, 0.f);
    }
    // 4) A = Qv @ R^T                         (8192 x 1025, ld 1028)
    {
        dim3 grid((twoM1 + BN - 1) / BN, ML / BM);
        sgemm_k<0, true><<<grid, blk>>>(pQv, pR, pA, nullptr, ML, twoM1, D, ldA,
                                        nullptr, nullptr, nullptr, 0, 0, 0, 0.f);
    }
    // 5) content + gather epilogue -> out     (per batch: 2048 x 2048)
    {
        dim3 grid(L / BN, L / BM, Bb);
        sgemm_k<2, false><<<grid, blk>>>(pQu, pK, out, nullptr, L, L, D, L,
                                         nullptr, nullptr, pA, ldA, L, maxrel, scale);
    }
}

// round 5
// speedup vs baseline: 2.9900x; 2.9900x over previous
#include <cuda_runtime.h>
#include <cuda_bf16.h>
#include <math.h>
#include <stdint.h>

// ---------------------------------------------------------------------------
// TransformerXL RPE via warp-level bf16 mma.sync split-GEMMs (sm_103 base
// target: tcgen05 unavailable in this build path; HMMA via mma.sync is).
//   Inputs split x = hi + lo (bf16 each); each GEMM computes
//   C = Ahi@Bhi^T + Alo@Bhi^T + Ahi@Blo^T  (3 K-segments, fp32 accum)
// Tiles: 128x128xBK64, 8 warps (2x4), warp tile 64x32 (4x4 m16n8k16),
// SW128 smem + ldmatrix, cp.async 2-stage pipeline, fused epilogues.
// Shapes: B=4, L=2048, D=1024, M_rel=512 (2M+1=1025 padded to 1280).
// ---------------------------------------------------------------------------

#define BMt 128
#define BNt 128
#define BKt 64            // bf16 per k-tile = 128 bytes
#define TT  48            // 3 segments x 16 k-tiles

// ---------------- scratch (device globals; allocation-free) ----------------
__device__ __nv_bfloat16 g_xs    [(size_t)8192 * 2048];
__device__ __nv_bfloat16 g_Wqs   [(size_t)1024 * 2048];
__device__ __nv_bfloat16 g_Wks   [(size_t)1024 * 2048];
__device__ __nv_bfloat16 g_Wrs   [(size_t)1024 * 2048];
__device__ __nv_bfloat16 g_tables[(size_t)1280 * 2048];
__device__ __nv_bfloat16 g_Qus   [(size_t)8192 * 2048];
__device__ __nv_bfloat16 g_Qvs   [(size_t)8192 * 2048];
__device__ __nv_bfloat16 g_Kbs   [(size_t)8192 * 2048];
__device__ __nv_bfloat16 g_Rs    [(size_t)1280 * 2048];
__device__ float         g_A     [(size_t)8192 * 1280];

#define SWZ(o) ((o) ^ (((o) >> 3) & 0x70))

__device__ __forceinline__ void cp16(uint32_t dst, const void* src) {
    asm volatile("cp.async.cg.shared.global [%0], [%1], 16;" :: "r"(dst), "l"(src));
}
__device__ __forceinline__ void cp_commit() { asm volatile("cp.async.commit_group;"); }
__device__ __forceinline__ void cp_wait1()  { asm volatile("cp.async.wait_group 1;" ::: "memory"); }
__device__ __forceinline__ void cp_wait0()  { asm volatile("cp.async.wait_group 0;" ::: "memory"); }

__device__ __forceinline__ void ldsm4(uint32_t* r, uint32_t addr) {
    asm volatile("ldmatrix.sync.aligned.m8n8.x4.shared.b16 {%0,%1,%2,%3}, [%4];"
                 : "=r"(r[0]), "=r"(r[1]), "=r"(r[2]), "=r"(r[3]) : "r"(addr));
}
__device__ __forceinline__ void mma16816(float* c, const uint32_t* a, const uint32_t* b) {
    asm volatile("mma.sync.aligned.m16n8k16.row.col.f32.bf16.bf16.f32 "
                 "{%0,%1,%2,%3}, {%4,%5,%6,%7}, {%8,%9}, {%0,%1,%2,%3};"
                 : "+f"(c[0]), "+f"(c[1]), "+f"(c[2]), "+f"(c[3])
                 : "r"(a[0]), "r"(a[1]), "r"(a[2]), "r"(a[3]), "r"(b[0]), "r"(b[1]));
}

// ---------------- input split conversion ----------------
__global__ void split_conv(const float* __restrict__ in, __nv_bfloat16* __restrict__ out,
                           int rows_in, int D, long n)
{
    long i = (long)blockIdx.x * blockDim.x + threadIdx.x;
    if (i >= n) return;
    int r = (int)(i / D);
    int c = (int)(i % D);
    float vv = (r < rows_in) ? in[(size_t)r * D + c] : 0.f;
    __nv_bfloat16 hi = __float2bfloat16(vv);
    float lo = vv - __bfloat162float(hi);
    out[(size_t)r * (2 * D) + c]     = hi;
    out[(size_t)r * (2 * D) + D + c] = __float2bfloat16(lo);
}

enum { M_SPLIT = 0, M_QUV = 1, M_F32 = 2, M_GATHER = 3 };

// ---------------- bf16 mma.sync GEMM, C = A@B^T over split K' = 3072 -------
template<int MODE>
__global__ void __launch_bounds__(256)
mma_gemm(const __nv_bfloat16* __restrict__ Ab, const __nv_bfloat16* __restrict__ Bb,
         __nv_bfloat16* __restrict__ S1, __nv_bfloat16* __restrict__ S2,
         float* __restrict__ O1, int ldo,
         const float* __restrict__ uvec, const float* __restrict__ vvec,
         const float* __restrict__ Pmat, int ldP, int maxrel, float scale, int Lrows)
{
    extern __shared__ char smem[];          // [2][A 16KB | B 16KB] = 64KB
    const int tid = threadIdx.x;
    const int wid = tid >> 5;
    const int lid = tid & 31;
    const uint32_t sbase = (uint32_t)__cvta_generic_to_shared(smem);

    const int row0 = blockIdx.y * BMt;
    const int col0 = blockIdx.x * BNt;

    const __nv_bfloat16* Aptr = Ab;
    const __nv_bfloat16* Bptr = Bb;
    if (MODE == M_GATHER) {
        size_t boff = (size_t)blockIdx.z * (size_t)Lrows * 2048;
        Aptr += boff; Bptr += boff;
    }

    const int wy = wid & 1;                 // 2 warp-rows of 64
    const int wx = wid >> 1;                // 4 warp-cols of 32

    // global->smem mapping: 128 rows x 8 x 16B per tile; 4 chunks/thread
    const int glr = tid >> 1;               // unused placeholder avoided below

    float acc[4][4][4];
    #pragma unroll
    for (int i = 0; i < 4; ++i)
        #pragma unroll
        for (int j = 0; j < 4; ++j)
            #pragma unroll
            for (int q = 0; q < 4; ++q) acc[i][j][q] = 0.f;

    auto issue_load = [&](int s, int ka, int kb) {
        const uint32_t aoff = sbase + s * 32768;
        const uint32_t boff = aoff + 16384;
        #pragma unroll
        for (int i = 0; i < 4; ++i) {
            int idx = tid + i * 256;        // 0..1023
            int r = idx >> 3, c = idx & 7;
            cp16(aoff + SWZ(r * 128 + c * 16),
                 Aptr + (size_t)(row0 + r) * 2048 + ka + c * 8);
        }
        #pragma unroll
        for (int i = 0; i < 4; ++i) {
            int idx = tid + i * 256;
            int r = idx >> 3, c = idx & 7;
            cp16(boff + SWZ(r * 128 + c * 16),
                 Bptr + (size_t)(col0 + r) * 2048 + kb + c * 8);
        }
        cp_commit();
    };

    auto kA = [](int t) { int seg = t >> 4; return (seg == 1 ? 1024 : 0) + (t & 15) * BKt; };
    auto kB = [](int t) { int seg = t >> 4; return (seg == 2 ? 1024 : 0) + (t & 15) * BKt; };

    issue_load(0, kA(0), kB(0));

    for (int t = 0; t < TT; ++t) {
        if (t + 1 < TT) { issue_load((t + 1) & 1, kA(t + 1), kB(t + 1)); cp_wait1(); }
        else            { cp_wait0(); }
        __syncthreads();

        const uint32_t aoff = sbase + (t & 1) * 32768;
        const uint32_t boff = aoff + 16384;

        #pragma unroll
        for (int ks = 0; ks < 4; ++ks) {
            const int kb2 = ks * 32;        // byte offset within 128B row
            uint32_t afr[4][4];
            #pragma unroll
            for (int im = 0; im < 4; ++im) {
                int r = wy * 64 + im * 16 + ((lid >> 3) & 1) * 8 + (lid & 7);
                ldsm4(afr[im], aoff + SWZ(r * 128 + kb2 + (lid >> 4) * 16));
            }
            uint32_t bfr[4][2];
            #pragma unroll
            for (int ib = 0; ib < 2; ++ib) {
                uint32_t rr[4];
                int nr = wx * 32 + ib * 16 + ((lid >> 4) & 1) * 8 + (lid & 7);
                ldsm4(rr, boff + SWZ(nr * 128 + kb2 + ((lid >> 3) & 1) * 16));
                bfr[ib * 2][0] = rr[0]; bfr[ib * 2][1] = rr[1];
                bfr[ib * 2 + 1][0] = rr[2]; bfr[ib * 2 + 1][1] = rr[3];
            }
            #pragma unroll
            for (int im = 0; im < 4; ++im)
                #pragma unroll
                for (int in = 0; in < 4; ++in)
                    mma16816(acc[im][in], afr[im], bfr[in]);
        }
        __syncthreads();
    }

    // ---------------- epilogue (direct from registers) ----------------
    #pragma unroll
    for (int im = 0; im < 4; ++im) {
        #pragma unroll
        for (int h = 0; h < 2; ++h) {
            const int rg = row0 + wy * 64 + im * 16 + (lid >> 2) + h * 8;
            #pragma unroll
            for (int in = 0; in < 4; ++in) {
                const int cg = col0 + wx * 32 + in * 8 + (lid & 3) * 2;
                const float v0 = acc[im][in][h * 2 + 0];
                const float v1 = acc[im][in][h * 2 + 1];

                if (MODE == M_SPLIT) {
                    __nv_bfloat16 h0 = __float2bfloat16(v0);
                    __nv_bfloat16 h1 = __float2bfloat16(v1);
                    __nv_bfloat162 hp; hp.x = h0; hp.y = h1;
                    __nv_bfloat162 lp;
                    lp.x = __float2bfloat16(v0 - __bfloat162float(h0));
                    lp.y = __float2bfloat16(v1 - __bfloat162float(h1));
                    *reinterpret_cast<__nv_bfloat162*>(S1 + (size_t)rg * 2048 + cg)        = hp;
                    *reinterpret_cast<__nv_bfloat162*>(S1 + (size_t)rg * 2048 + 1024 + cg) = lp;
                } else if (MODE == M_QUV) {
                    float q0 = v0 + uvec[cg], q1 = v1 + uvec[cg + 1];
                    float w0 = v0 + vvec[cg], w1 = v1 + vvec[cg + 1];
                    __nv_bfloat16 qh0 = __float2bfloat16(q0), qh1 = __float2bfloat16(q1);
                    __nv_bfloat16 wh0 = __float2bfloat16(w0), wh1 = __float2bfloat16(w1);
                    __nv_bfloat162 p;
                    p.x = qh0; p.y = qh1;
                    *reinterpret_cast<__nv_bfloat162*>(S1 + (size_t)rg * 2048 + cg) = p;
                    p.x = __float2bfloat16(q0 - __bfloat162float(qh0));
                    p.y = __float2bfloat16(q1 - __bfloat162float(qh1));
                    *reinterpret_cast<__nv_bfloat162*>(S1 + (size_t)rg * 2048 + 1024 + cg) = p;
                    p.x = wh0; p.y = wh1;
                    *reinterpret_cast<__nv_bfloat162*>(S2 + (size_t)rg * 2048 + cg) = p;
                    p.x = __float2bfloat16(w0 - __bfloat162float(wh0));
                    p.y = __float2bfloat16(w1 - __bfloat162float(wh1));
                    *reinterpret_cast<__nv_bfloat162*>(S2 + (size_t)rg * 2048 + 1024 + cg) = p;
                } else if (MODE == M_F32) {
                    float2 o; o.x = v0; o.y = v1;
                    *reinterpret_cast<float2*>(O1 + (size_t)rg * ldo + cg) = o;
                } else { // M_GATHER
                    const size_t grow = (size_t)blockIdx.z * Lrows + rg;
                    int d0 = rg - cg;
                    int d1 = d0 - 1;
                    d0 = d0 < -maxrel ? -maxrel : (d0 > maxrel ? maxrel : d0);
                    d1 = d1 < -maxrel ? -maxrel : (d1 > maxrel ? maxrel : d1);
                    const float* prow = Pmat + grow * (size_t)ldP + maxrel;
                    float2 o;
                    o.x = (v0 + prow[d0]) * scale;
                    o.y = (v1 + prow[d1]) * scale;
                    *reinterpret_cast<float2*>(O1 + grow * (size_t)ldo + cg) = o;
                }
            }
        }
    }
}

// ---------------- host ----------------
extern "C" void kernel_launch(void* const* d_in, const int* in_sizes, int n_in,
                              void* d_out, int out_size)
{
    const float* x     = (const float*)d_in[0];
    const float* Wq    = (const float*)d_in[1];
    const float* Wk    = (const float*)d_in[2];
    const float* Wr    = (const float*)d_in[3];
    const float* u     = (const float*)d_in[4];
    const float* v     = (const float*)d_in[5];
    const float* table = (const float*)d_in[6];
    float* out = (float*)d_out;

    const int D      = in_sizes[4];            // 1024
    const int ML     = in_sizes[0] / D;        // 8192
    const int L      = out_size / ML;          // 2048
    const int Bb     = ML / L;                 // 4
    const int twoM1  = in_sizes[6] / D;        // 1025
    const int maxrel = (twoM1 - 1) / 2;        // 512
    const int NPAD   = 1280;
    const float scale = 1.0f / sqrtf((float)D);
    const int SMEM = 65536;

    static bool init_done = false;
    static __nv_bfloat16 *pxs, *pWqs, *pWks, *pWrs, *ptbl, *pQus, *pQvs, *pKbs, *pRs;
    static float* pA;
    if (!init_done) {
        cudaGetSymbolAddress((void**)&pxs,  g_xs);
        cudaGetSymbolAddress((void**)&pWqs, g_Wqs);
        cudaGetSymbolAddress((void**)&pWks, g_Wks);
        cudaGetSymbolAddress((void**)&pWrs, g_Wrs);
        cudaGetSymbolAddress((void**)&ptbl, g_tables);
        cudaGetSymbolAddress((void**)&pQus, g_Qus);
        cudaGetSymbolAddress((void**)&pQvs, g_Qvs);
        cudaGetSymbolAddress((void**)&pKbs, g_Kbs);
        cudaGetSymbolAddress((void**)&pRs,  g_Rs);
        cudaGetSymbolAddress((void**)&pA,   g_A);
        cudaFuncSetAttribute(mma_gemm<M_SPLIT>,  cudaFuncAttributeMaxDynamicSharedMemorySize, SMEM);
        cudaFuncSetAttribute(mma_gemm<M_QUV>,    cudaFuncAttributeMaxDynamicSharedMemorySize, SMEM);
        cudaFuncSetAttribute(mma_gemm<M_F32>,    cudaFuncAttributeMaxDynamicSharedMemorySize, SMEM);
        cudaFuncSetAttribute(mma_gemm<M_GATHER>, cudaFuncAttributeMaxDynamicSharedMemorySize, SMEM);
        init_done = true;
    }

    // ---- input splits ----
    {
        long n;
        n = (long)ML * D;
        split_conv<<<(unsigned)((n + 255) / 256), 256>>>(x, pxs, ML, D, n);
        n = (long)D * D;
        split_conv<<<(unsigned)((n + 255) / 256), 256>>>(Wq, pWqs, D, D, n);
        split_conv<<<(unsigned)((n + 255) / 256), 256>>>(Wk, pWks, D, D, n);
        split_conv<<<(unsigned)((n + 255) / 256), 256>>>(Wr, pWrs, D, D, n);
        n = (long)NPAD * D;
        split_conv<<<(unsigned)((n + 255) / 256), 256>>>(table, ptbl, twoM1, D, n);
    }

    dim3 blk(256);

    // 1) Q = x@Wq^T -> Qu/Qv splits       (8192 x 1024)
    mma_gemm<M_QUV><<<dim3(D / BNt, ML / BMt), blk, SMEM>>>(
        pxs, pWqs, pQus, pQvs, nullptr, 0, u, v, nullptr, 0, 0, 0.f, 0);

    // 2) K = x@Wk^T -> Kb split           (8192 x 1024)
    mma_gemm<M_SPLIT><<<dim3(D / BNt, ML / BMt), blk, SMEM>>>(
        pxs, pWks, pKbs, nullptr, nullptr, 0, nullptr, nullptr, nullptr, 0, 0, 0.f, 0);

    // 3) R = table@Wr^T -> R split        (1280 x 1024, padded rows = 0)
    mma_gemm<M_SPLIT><<<dim3(D / BNt, NPAD / BMt), blk, SMEM>>>(
        ptbl, pWrs, pRs, nullptr, nullptr, 0, nullptr, nullptr, nullptr, 0, 0, 0.f, 0);

    // 4) A = Qv@R^T  (fp32)               (8192 x 1280)
    mma_gemm<M_F32><<<dim3(NPAD / BNt, ML / BMt), blk, SMEM>>>(
        pQvs, pRs, nullptr, nullptr, pA, NPAD, nullptr, nullptr, nullptr, 0, 0, 0.f, 0);

    // 5) content + gather -> out          (per batch 2048 x 2048)
    mma_gemm<M_GATHER><<<dim3(L / BNt, L / BMt, Bb), blk, SMEM>>>(
        pQus, pKbs, nullptr, nullptr, out, L, nullptr, nullptr, pA, NPAD, maxrel, scale, L);
}